// round 16
// baseline (speedup 1.0000x reference)
#include <cuda_runtime.h>
#include <math.h>
#include <stdint.h>

// ===========================================================================
// Baseline-PTX helpers (ldmatrix + mma.sync + cp.async). No tcgen05.
// ===========================================================================
__device__ __forceinline__ uint32_t smem_u32(const void* p) {
    uint32_t a;
    asm("{ .reg .u64 t; cvta.to.shared.u64 t, %1; cvt.u32.u64 %0, t; }" : "=r"(a) : "l"(p));
    return a;
}
__device__ __forceinline__ void ldsm_x4(uint32_t r[4], uint32_t addr) {
    asm volatile("ldmatrix.sync.aligned.m8n8.x4.shared.b16 {%0,%1,%2,%3}, [%4];"
                 : "=r"(r[0]), "=r"(r[1]), "=r"(r[2]), "=r"(r[3]) : "r"(addr));
}
__device__ __forceinline__ void mma_s8(int c[4], const uint32_t a[4],
                                       uint32_t b0, uint32_t b1) {
    asm volatile(
        "mma.sync.aligned.m16n8k32.row.col.s32.s8.s8.s32 "
        "{%0,%1,%2,%3}, {%4,%5,%6,%7}, {%8,%9}, {%0,%1,%2,%3};"
        : "+r"(c[0]), "+r"(c[1]), "+r"(c[2]), "+r"(c[3])
        : "r"(a[0]), "r"(a[1]), "r"(a[2]), "r"(a[3]), "r"(b0), "r"(b1));
}
__device__ __forceinline__ void cp16(uint32_t dst, const void* src) {
    asm volatile("cp.async.cg.shared.global [%0], [%1], 16;" ::"r"(dst), "l"(src));
}
#define CP_COMMIT() asm volatile("cp.async.commit_group;" ::: "memory")
#define CP_WAIT1() asm volatile("cp.async.wait_group 1;" ::: "memory")

// ===========================================================================
// Scratch (device globals)
// ===========================================================================
__device__ float g_h1[256 * 256 * 400];
__device__ float g_uraw[256 * 9216];
__device__ float g_uT[9216 * 256];
__device__ float g_blog[10 * 1152 * 16];
__device__ float g_probs[10 * 1152 * 16];
__device__ float g_spart[10 * 32 * 16 * 256];
__device__ float g_v[10 * 16 * 256];
__device__ char g_w2h8[256 * 20736];    // int8 hi limb of w2 (row-scaled)
__device__ char g_w2l8[256 * 20736];    // int8 lo limb
__device__ char g_bqh[9216 * 20736];    // im2col B, hi limb (per-batch scaled)
__device__ char g_bql[9216 * 20736];    // im2col B, lo limb
__device__ float g_dsA[256];            // dequant scale per oc row
__device__ float g_dsB[256];            // dequant scale per batch
__device__ float g_qB[256];             // quant scale per batch (16256/max)
__device__ int g_koff[20736];           // im2col k -> h1 offset (input-indep)

// ===========================================================================
// conv1 (unchanged, known-good)
// ===========================================================================
__global__ __launch_bounds__(128) void conv1_kernel(const float* __restrict__ x,
                                                    const float* __restrict__ w,
                                                    const float* __restrict__ bias) {
    int b = blockIdx.x, ocg = blockIdx.y;
    __shared__ float xs[784];
    __shared__ float ws[16 * 81];
    int tid = threadIdx.x;
    for (int i = tid; i < 784; i += 128) xs[i] = x[b * 784 + i];
    for (int i = tid; i < 1296; i += 128) ws[i] = w[ocg * 1296 + i];
    __syncthreads();

    int pr[4], pc[4];
    bool val[4];
#pragma unroll
    for (int q = 0; q < 4; q++) {
        int p = tid + q * 128;
        val[q] = (p < 400);
        int pp = val[q] ? p : 0;
        pr[q] = pp / 20;
        pc[q] = pp % 20;
    }
    float acc[4][16];
#pragma unroll
    for (int q = 0; q < 4; q++)
#pragma unroll
        for (int o = 0; o < 16; o++) acc[q][o] = 0.f;

#pragma unroll 1
    for (int kh = 0; kh < 9; kh++) {
        int rb[4];
#pragma unroll
        for (int q = 0; q < 4; q++) rb[q] = (pr[q] + kh) * 28 + pc[q];
#pragma unroll 1
        for (int kw = 0; kw < 9; kw++) {
            float xv[4];
#pragma unroll
            for (int q = 0; q < 4; q++) xv[q] = xs[rb[q] + kw];
            int ko = kh * 9 + kw;
#pragma unroll
            for (int o = 0; o < 16; o++) {
                float wv = ws[o * 81 + ko];
#pragma unroll
                for (int q = 0; q < 4; q++) acc[q][o] = fmaf(xv[q], wv, acc[q][o]);
            }
        }
    }
#pragma unroll
    for (int o = 0; o < 16; o++) {
        float bv = bias[ocg * 16 + o];
#pragma unroll
        for (int q = 0; q < 4; q++) {
            if (val[q]) {
                float v = acc[q][o] + bv;
                g_h1[(b * 256 + ocg * 16 + o) * 400 + tid + q * 128] = fmaxf(v, 0.f);
            }
        }
    }
}

// ===========================================================================
// merged prep: blocks 0-255 = A quantize (per-oc-row), 256-511 = B per-batch
// max, 512-592 = koff table build.
// ===========================================================================
__global__ __launch_bounds__(256) void prep_kernel(const float* __restrict__ w2) {
    int blk = blockIdx.x, tid = threadIdx.x;
    if (blk >= 512) {  // koff table
        int k = (blk - 512) * 256 + tid;
        if (k < 20736) {
            int ic = k / 81, rr = k - ic * 81;
            g_koff[k] = ic * 400 + (rr / 9) * 20 + (rr % 9);
        }
        return;
    }
    __shared__ float red[256];
    if (blk < 256) {  // A: row max + 2-limb quantize
        int m = blk;
        const float* row = &w2[(size_t)m * 20736];
        float mx = 0.f;
        for (int k = tid; k < 20736; k += 256) mx = fmaxf(mx, fabsf(row[k]));
        red[tid] = mx;
        __syncthreads();
        for (int s = 128; s > 0; s >>= 1) {
            if (tid < s) red[tid] = fmaxf(red[tid], red[tid + s]);
            __syncthreads();
        }
        mx = red[0];
        if (tid == 0) g_dsA[m] = mx * (1.0f / 16256.0f);
        float qa = mx > 0.f ? 16256.0f / mx : 0.f;
        for (int k = tid; k < 20736; k += 256) {
            float a15 = rintf(row[k] * qa);
            float ahf = rintf(a15 * (1.0f / 128.0f));
            int ah = (int)ahf;
            int al = (int)(a15 - 128.0f * ahf);
            g_w2h8[(size_t)m * 20736 + k] = (char)ah;
            g_w2l8[(size_t)m * 20736 + k] = (char)al;
        }
    } else {  // B: per-batch max of h1
        int b = blk - 256;
        const float* sl = &g_h1[(size_t)b * 102400];
        float mx = 0.f;
        for (int i = tid; i < 102400; i += 256) mx = fmaxf(mx, sl[i]);
        red[tid] = mx;
        __syncthreads();
        for (int s = 128; s > 0; s >>= 1) {
            if (tid < s) red[tid] = fmaxf(red[tid], red[tid + s]);
            __syncthreads();
        }
        if (tid == 0) {
            float m = red[0];
            g_dsB[b] = m * (1.0f / 16256.0f);
            g_qB[b] = m > 0.f ? 16256.0f / m : 0.f;
        }
    }
}

// ===========================================================================
// bquant: im2col B -> two int8 limb planes, via koff lookup (no divisions).
// ===========================================================================
__global__ __launch_bounds__(256) void bquant_kernel() {
    int n = blockIdx.x;
    int bb = n / 36, s = n - bb * 36;
    int base = bb * 102400 + (s / 6) * 40 + (s % 6) * 2;
    float qb = g_qB[bb];
    size_t rowo = (size_t)n * 20736;
    const float* h1b = g_h1 + base;
    for (int k0 = threadIdx.x * 8; k0 < 20736; k0 += 2048) {
        int4 ko0 = *(const int4*)&g_koff[k0];
        int4 ko1 = *(const int4*)&g_koff[k0 + 4];
        int hi[8], lo[8];
        float v[8];
        v[0] = h1b[ko0.x]; v[1] = h1b[ko0.y]; v[2] = h1b[ko0.z]; v[3] = h1b[ko0.w];
        v[4] = h1b[ko1.x]; v[5] = h1b[ko1.y]; v[6] = h1b[ko1.z]; v[7] = h1b[ko1.w];
#pragma unroll
        for (int j = 0; j < 8; j++) {
            int s16 = __float2int_rn(v[j] * qb);
            hi[j] = (s16 + 64) >> 7;
            lo[j] = s16 - (hi[j] << 7);
        }
        uint32_t ph0 = __byte_perm(__byte_perm(hi[0], hi[1], 0x0040),
                                   __byte_perm(hi[2], hi[3], 0x0040), 0x5410);
        uint32_t ph1 = __byte_perm(__byte_perm(hi[4], hi[5], 0x0040),
                                   __byte_perm(hi[6], hi[7], 0x0040), 0x5410);
        uint32_t pl0 = __byte_perm(__byte_perm(lo[0], lo[1], 0x0040),
                                   __byte_perm(lo[2], lo[3], 0x0040), 0x5410);
        uint32_t pl1 = __byte_perm(__byte_perm(lo[4], lo[5], 0x0040),
                                   __byte_perm(lo[6], lo[7], 0x0040), 0x5410);
        *(uint2*)(g_bqh + rowo + k0) = make_uint2(ph0, ph1);
        *(uint2*)(g_bql + rowo + k0) = make_uint2(pl0, pl1);
    }
}

// ===========================================================================
// conv2: pure int8 GEMM (2-limb, 3 MMAs per k32), pass-reordered.
// M=256 x N=9216 x K=20736; grid (2,144), 256 thr / 8 warps; warp tile 32x32.
// BK=64, 3-stage cp.async ring.
// ===========================================================================
#define ROWB 80
#define PLANE_A (128 * ROWB)               // 10240
#define PLANE_B (64 * ROWB)                // 5120
#define STG (2 * PLANE_A + 2 * PLANE_B)    // 30720 per stage (Ah|Al|Bh|Bl)
#define NSTAGE 324

__global__ __launch_bounds__(256, 2) void conv2_mma_kernel(const float* __restrict__ b2) {
    extern __shared__ __align__(16) unsigned char sm[];

    const int tid = threadIdx.x, lane = tid & 31, wid = tid >> 5;
    const int m0 = blockIdx.x * 128, n0 = blockIdx.y * 64;
    const int wm0 = (wid & 3) * 32;
    const int wn0 = (wid >> 2) * 32;
    const uint32_t sb = smem_u32(sm);

    int hh[2][4][4], cr[2][4][4];
#pragma unroll
    for (int mi = 0; mi < 2; mi++)
#pragma unroll
        for (int nt = 0; nt < 4; nt++)
#pragma unroll
            for (int q = 0; q < 4; q++) { hh[mi][nt][q] = 0; cr[mi][nt][q] = 0; }

    auto issue = [&](uint32_t base, int kt) {
#pragma unroll
        for (int q = 0; q < 4; q++) {
            int id = q * 256 + tid;
            int plane = id >> 9;
            int rem = id & 511;
            int row = rem >> 2;
            int c16 = rem & 3;
            const char* src = plane ? g_w2l8 : g_w2h8;
            cp16(base + plane * PLANE_A + row * ROWB + c16 * 16,
                 src + (size_t)(m0 + row) * 20736 + kt + c16 * 16);
        }
#pragma unroll
        for (int q = 0; q < 2; q++) {
            int id = q * 256 + tid;
            int plane = id >> 8;
            int rem = id & 255;
            int row = rem >> 2;
            int c16 = rem & 3;
            const char* src = plane ? g_bql : g_bqh;
            cp16(base + 2 * PLANE_A + plane * PLANE_B + row * ROWB + c16 * 16,
                 src + (size_t)(n0 + row) * 20736 + kt + c16 * 16);
        }
        CP_COMMIT();
    };

    issue(sb, 0);
    issue(sb + STG, 64);

    for (int s = 0; s < NSTAGE; s++) {
        const uint32_t cb = sb + (uint32_t)(s % 3) * STG;
        CP_WAIT1();
        __syncthreads();
        if (s + 2 < NSTAGE) issue(sb + (uint32_t)((s + 2) % 3) * STG, (s + 2) * 64);

#pragma unroll
        for (int ks = 0; ks < 2; ks++) {
            uint32_t ah[2][4], al[2][4];
#pragma unroll
            for (int mi = 0; mi < 2; mi++) {
                uint32_t ra = (uint32_t)((wm0 + mi * 16 + (lane & 15)) * ROWB +
                                         ks * 32 + ((lane >> 4) << 4));
                ldsm_x4(ah[mi], cb + ra);
                ldsm_x4(al[mi], cb + PLANE_A + ra);
            }
            uint32_t bh[2][4], bl[2][4];
#pragma unroll
            for (int g = 0; g < 2; g++) {
                uint32_t rb = (uint32_t)((wn0 + g * 16 + (lane & 7) + ((lane >> 4) << 3)) * ROWB +
                                         ks * 32 + (((lane >> 3) & 1) << 4));
                ldsm_x4(bh[g], cb + 2 * PLANE_A + rb);
                ldsm_x4(bl[g], cb + 2 * PLANE_A + PLANE_B + rb);
            }
            // pass 1: hh += ah*bh
#pragma unroll
            for (int mi = 0; mi < 2; mi++)
#pragma unroll
                for (int g = 0; g < 2; g++)
#pragma unroll
                    for (int h = 0; h < 2; h++)
                        mma_s8(hh[mi][g * 2 + h], ah[mi], bh[g][2 * h], bh[g][2 * h + 1]);
            // pass 2: cr += ah*bl
#pragma unroll
            for (int mi = 0; mi < 2; mi++)
#pragma unroll
                for (int g = 0; g < 2; g++)
#pragma unroll
                    for (int h = 0; h < 2; h++)
                        mma_s8(cr[mi][g * 2 + h], ah[mi], bl[g][2 * h], bl[g][2 * h + 1]);
            // pass 3: cr += al*bh
#pragma unroll
            for (int mi = 0; mi < 2; mi++)
#pragma unroll
                for (int g = 0; g < 2; g++)
#pragma unroll
                    for (int h = 0; h < 2; h++)
                        mma_s8(cr[mi][g * 2 + h], al[mi], bh[g][2 * h], bh[g][2 * h + 1]);
        }
    }

#pragma unroll
    for (int mi = 0; mi < 2; mi++) {
        int r0 = m0 + wm0 + mi * 16 + (lane >> 2);
        int r1 = r0 + 8;
        float sa0 = g_dsA[r0], sa1 = g_dsA[r1];
        float bias0 = b2[r0], bias1 = b2[r1];
#pragma unroll
        for (int nt = 0; nt < 4; nt++) {
            int c0 = n0 + wn0 + nt * 8 + ((lane & 3) << 1);
            int c1 = c0 + 1;
            int bb0 = c0 / 36, ss0 = c0 - bb0 * 36;
            int bb1 = c1 / 36, ss1 = c1 - bb1 * 36;
            float s0 = g_dsB[bb0], s1 = g_dsB[bb1];
            g_uraw[bb0 * 9216 + ss0 + r0 * 36] =
                sa0 * s0 * (16384.f * (float)hh[mi][nt][0] + 128.f * (float)cr[mi][nt][0]) + bias0;
            g_uraw[bb1 * 9216 + ss1 + r0 * 36] =
                sa0 * s1 * (16384.f * (float)hh[mi][nt][1] + 128.f * (float)cr[mi][nt][1]) + bias0;
            g_uraw[bb0 * 9216 + ss0 + r1 * 36] =
                sa1 * s0 * (16384.f * (float)hh[mi][nt][2] + 128.f * (float)cr[mi][nt][2]) + bias1;
            g_uraw[bb1 * 9216 + ss1 + r1 * 36] =
                sa1 * s1 * (16384.f * (float)hh[mi][nt][3] + 128.f * (float)cr[mi][nt][3]) + bias1;
        }
    }
}

// ===========================================================================
// primary squash + transpose
// ===========================================================================
__global__ __launch_bounds__(256) void squashT_kernel() {
    int idx = blockIdx.x * 256 + threadIdx.x;
    int n = idx >> 8, b = idx & 255;
    const float4* src = (const float4*)&g_uraw[b * 9216 + n * 8];
    float4 u0 = src[0], u1 = src[1];
    float sq = u0.x * u0.x + u0.y * u0.y + u0.z * u0.z + u0.w * u0.w +
               u1.x * u1.x + u1.y * u1.y + u1.z * u1.z + u1.w * u1.w;
    float sc = sq / (1.0f + sq);
    float r[8] = {u0.x * sc, u0.y * sc, u0.z * sc, u0.w * sc,
                  u1.x * sc, u1.y * sc, u1.z * sc, u1.w * sc};
#pragma unroll
    for (int j = 0; j < 8; j++) g_uT[(n * 8 + j) * 256 + b] = r[j];
}

__global__ __launch_bounds__(128) void softmax_kernel() {
    int c = blockIdx.x >> 4, i = blockIdx.x & 15;
    int tid = threadIdx.x;
    __shared__ float red[128];
    float vals[9];
    float m = -1e30f;
#pragma unroll
    for (int q = 0; q < 9; q++) {
        int n = tid + q * 128;
        vals[q] = g_blog[(c * 1152 + n) * 16 + i];
        m = fmaxf(m, vals[q]);
    }
    red[tid] = m;
    __syncthreads();
    for (int s2 = 64; s2 > 0; s2 >>= 1) {
        if (tid < s2) red[tid] = fmaxf(red[tid], red[tid + s2]);
        __syncthreads();
    }
    float M = red[0];
    __syncthreads();
    float e[9];
    float sum = 0.f;
#pragma unroll
    for (int q = 0; q < 9; q++) {
        e[q] = expf(vals[q] - M);
        sum += e[q];
    }
    red[tid] = sum;
    __syncthreads();
    for (int s2 = 64; s2 > 0; s2 >>= 1) {
        if (tid < s2) red[tid] += red[tid + s2];
        __syncthreads();
    }
    float inv = 1.0f / red[0];
#pragma unroll
    for (int q = 0; q < 9; q++)
        g_probs[(c * 1152 + tid + q * 128) * 16 + i] = e[q] * inv;
}

// ===========================================================================
// s partial GEMM: 32 n-chunks of 36. uniform=1: probs = 1/1152 (iter 0).
// ===========================================================================
__global__ __launch_bounds__(128) void sgemm_routing_kernel(const float* __restrict__ W,
                                                            int uniform) {
    int nc = blockIdx.x, c = blockIdx.y;
    int tid = threadIdx.x;
    int ig = tid >> 5, bg = tid & 31;
    int i0 = ig << 2;
    __shared__ float uu[2048];
    __shared__ float pw[128];
    int pi = tid >> 3, pj = tid & 7;

    float acc[4][8];
#pragma unroll
    for (int ii = 0; ii < 4; ii++)
#pragma unroll
        for (int bi = 0; bi < 8; bi++) acc[ii][bi] = 0.f;

    for (int n = nc * 36; n < nc * 36 + 36; ++n) {
        __syncthreads();
        const float4* src = (const float4*)&g_uT[n * 2048];
#pragma unroll
        for (int q = 0; q < 4; q++) ((float4*)uu)[tid + q * 128] = src[tid + q * 128];
        float p = uniform ? (1.0f / 1152.0f) : g_probs[(c * 1152 + n) * 16 + pi];
        pw[tid] = p * W[((c * 1152 + n) * 16 + pi) * 8 + pj];
        __syncthreads();

        float pwv[4][8];
#pragma unroll
        for (int ii = 0; ii < 4; ii++)
#pragma unroll
            for (int j = 0; j < 8; j++) pwv[ii][j] = pw[(i0 + ii) * 8 + j];

#pragma unroll
        for (int bi = 0; bi < 8; bi++) {
            int b = bg + (bi << 5);
            float uv[8];
#pragma unroll
            for (int j = 0; j < 8; j++) uv[j] = uu[j * 256 + b];
#pragma unroll
            for (int ii = 0; ii < 4; ii++)
#pragma unroll
                for (int j = 0; j < 8; j++)
                    acc[ii][bi] = fmaf(pwv[ii][j], uv[j], acc[ii][bi]);
        }
    }
#pragma unroll
    for (int ii = 0; ii < 4; ii++)
#pragma unroll
        for (int bi = 0; bi < 8; bi++)
            g_spart[((c * 32 + nc) * 16 + i0 + ii) * 256 + bg + (bi << 5)] = acc[ii][bi];
}

__global__ __launch_bounds__(256) void squashv_kernel() {
    int c = blockIdx.x >> 4, i = blockIdx.x & 15;
    int tid = threadIdx.x;
    float sv = 0.f;
#pragma unroll
    for (int ch = 0; ch < 32; ch++)
        sv += g_spart[((c * 32 + ch) * 16 + i) * 256 + tid];
    __shared__ float red[256];
    red[tid] = sv * sv;
    __syncthreads();
    for (int s2 = 128; s2 > 0; s2 >>= 1) {
        if (tid < s2) red[tid] += red[tid + s2];
        __syncthreads();
    }
    float sq = red[0];
    float scale = sq / ((1.0f + sq) * sqrtf(sq));
    g_v[(c * 16 + i) * 256 + tid] = sv * scale;
}

// store=1: first delta (blog starts undefined; overwrite). Else accumulate.
__global__ __launch_bounds__(128) void delta_kernel(const float* __restrict__ W,
                                                    int store) {
    int n0 = blockIdx.x * 8, c = blockIdx.y;
    int tid = threadIdx.x;
    int nl = tid >> 4, i = tid & 15;
    int n = n0 + nl;
    __shared__ float vsh[16 * 257];
    __shared__ float ush[2048];
    float wr[8];
    const float* wp = &W[((c * 1152 + n) * 16 + i) * 8];
#pragma unroll
    for (int j = 0; j < 8; j++) wr[j] = wp[j];
#pragma unroll
    for (int q = 0; q < 32; q++) {
        int idx = tid + q * 128;
        vsh[(idx >> 8) * 257 + (idx & 255)] = g_v[c * 4096 + idx];
    }
    float acc = 0.f;
    for (int bc = 0; bc < 8; bc++) {
        __syncthreads();
#pragma unroll
        for (int q = 0; q < 16; q++) {
            int f = tid + q * 128;
            ush[f] = g_uT[(n0 * 8 + (f >> 5)) * 256 + (bc << 5) + (f & 31)];
        }
        __syncthreads();
#pragma unroll 4
        for (int bb = 0; bb < 32; bb++) {
            int b = (bc << 5) + bb;
            float uh = 0.f;
#pragma unroll
            for (int j = 0; j < 8; j++)
                uh = fmaf(wr[j], ush[(nl * 8 + j) * 32 + bb], uh);
            acc = fmaf(uh, vsh[i * 257 + b], acc);
        }
    }
    int idx = (c * 1152 + n) * 16 + i;
    g_blog[idx] = store ? acc : (g_blog[idx] + acc);
}

__global__ void out_kernel(float* __restrict__ out) {
    int c = blockIdx.x, b = threadIdx.x;
    float s = 0.f;
#pragma unroll
    for (int i = 0; i < 16; i++) {
        float t = g_v[(c * 16 + i) * 256 + b];
        s = fmaf(t, t, s);
    }
    out[b * 10 + c] = s;
}

// ===========================================================================
extern "C" void kernel_launch(void* const* d_in, const int* in_sizes, int n_in,
                              void* d_out, int out_size) {
    const float* x  = (const float*)d_in[0];
    const float* w1 = (const float*)d_in[1];
    const float* b1 = (const float*)d_in[2];
    const float* w2 = (const float*)d_in[3];
    const float* b2 = (const float*)d_in[4];
    const float* W  = (const float*)d_in[5];
    float* out = (float*)d_out;

    const int SMEM_BYTES = 3 * STG;  // 92160
    cudaFuncSetAttribute(conv2_mma_kernel, cudaFuncAttributeMaxDynamicSharedMemorySize,
                         SMEM_BYTES);

    conv1_kernel<<<dim3(256, 16), 128>>>(x, w1, b1);
    prep_kernel<<<593, 256>>>(w2);
    bquant_kernel<<<9216, 256>>>();
    conv2_mma_kernel<<<dim3(2, 144), 256, SMEM_BYTES>>>(b2);
    squashT_kernel<<<1152, 256>>>();

    for (int it = 0; it < 3; it++) {
        if (it > 0) softmax_kernel<<<160, 128>>>();
        sgemm_routing_kernel<<<dim3(32, 10), 128>>>(W, it == 0 ? 1 : 0);
        squashv_kernel<<<160, 256>>>();
        if (it < 2) delta_kernel<<<dim3(144, 10), 128>>>(W, it == 0 ? 1 : 0);
    }
    out_kernel<<<10, 256>>>(out);
}

// round 17
// speedup vs baseline: 1.0507x; 1.0507x over previous
#include <cuda_runtime.h>
#include <math.h>
#include <stdint.h>

// ===========================================================================
// Baseline-PTX helpers (ldmatrix + mma.sync + cp.async). No tcgen05.
// ===========================================================================
__device__ __forceinline__ uint32_t smem_u32(const void* p) {
    uint32_t a;
    asm("{ .reg .u64 t; cvta.to.shared.u64 t, %1; cvt.u32.u64 %0, t; }" : "=r"(a) : "l"(p));
    return a;
}
__device__ __forceinline__ void ldsm_x4(uint32_t r[4], uint32_t addr) {
    asm volatile("ldmatrix.sync.aligned.m8n8.x4.shared.b16 {%0,%1,%2,%3}, [%4];"
                 : "=r"(r[0]), "=r"(r[1]), "=r"(r[2]), "=r"(r[3]) : "r"(addr));
}
__device__ __forceinline__ void mma_s8(int c[4], const uint32_t a[4],
                                       uint32_t b0, uint32_t b1) {
    asm volatile(
        "mma.sync.aligned.m16n8k32.row.col.s32.s8.s8.s32 "
        "{%0,%1,%2,%3}, {%4,%5,%6,%7}, {%8,%9}, {%0,%1,%2,%3};"
        : "+r"(c[0]), "+r"(c[1]), "+r"(c[2]), "+r"(c[3])
        : "r"(a[0]), "r"(a[1]), "r"(a[2]), "r"(a[3]), "r"(b0), "r"(b1));
}
__device__ __forceinline__ void cp16(uint32_t dst, const void* src) {
    asm volatile("cp.async.cg.shared.global [%0], [%1], 16;" ::"r"(dst), "l"(src));
}
#define CP_COMMIT() asm volatile("cp.async.commit_group;" ::: "memory")
#define CP_WAIT0() asm volatile("cp.async.wait_group 0;" ::: "memory")

// ===========================================================================
// Scratch (device globals)
// ===========================================================================
__device__ float g_h1[256 * 256 * 400];
__device__ float g_uraw[256 * 9216];
__device__ float g_uT[9216 * 256];
__device__ float g_blog[10 * 1152 * 16];
__device__ float g_probs[10 * 1152 * 16];
__device__ float g_spart[10 * 32 * 16 * 256];
__device__ float g_v[10 * 16 * 256];
__device__ char g_w2h8[256 * 20736];    // int8 hi limb of w2 (row-scaled)
__device__ char g_w2l8[256 * 20736];    // int8 lo limb
__device__ char g_bqh[9216 * 20736];    // im2col B, hi limb (per-batch scaled)
__device__ char g_bql[9216 * 20736];    // im2col B, lo limb
__device__ float g_dsA[256];            // dequant scale per oc row
__device__ float g_dsB[256];            // dequant scale per batch
__device__ float g_qB[256];             // quant scale per batch (16256/max)
__device__ int g_koff[20736];           // im2col k -> h1 offset (input-indep)

// ===========================================================================
// conv1 (unchanged, known-good)
// ===========================================================================
__global__ __launch_bounds__(128) void conv1_kernel(const float* __restrict__ x,
                                                    const float* __restrict__ w,
                                                    const float* __restrict__ bias) {
    int b = blockIdx.x, ocg = blockIdx.y;
    __shared__ float xs[784];
    __shared__ float ws[16 * 81];
    int tid = threadIdx.x;
    for (int i = tid; i < 784; i += 128) xs[i] = x[b * 784 + i];
    for (int i = tid; i < 1296; i += 128) ws[i] = w[ocg * 1296 + i];
    __syncthreads();

    int pr[4], pc[4];
    bool val[4];
#pragma unroll
    for (int q = 0; q < 4; q++) {
        int p = tid + q * 128;
        val[q] = (p < 400);
        int pp = val[q] ? p : 0;
        pr[q] = pp / 20;
        pc[q] = pp % 20;
    }
    float acc[4][16];
#pragma unroll
    for (int q = 0; q < 4; q++)
#pragma unroll
        for (int o = 0; o < 16; o++) acc[q][o] = 0.f;

#pragma unroll 1
    for (int kh = 0; kh < 9; kh++) {
        int rb[4];
#pragma unroll
        for (int q = 0; q < 4; q++) rb[q] = (pr[q] + kh) * 28 + pc[q];
#pragma unroll 1
        for (int kw = 0; kw < 9; kw++) {
            float xv[4];
#pragma unroll
            for (int q = 0; q < 4; q++) xv[q] = xs[rb[q] + kw];
            int ko = kh * 9 + kw;
#pragma unroll
            for (int o = 0; o < 16; o++) {
                float wv = ws[o * 81 + ko];
#pragma unroll
                for (int q = 0; q < 4; q++) acc[q][o] = fmaf(xv[q], wv, acc[q][o]);
            }
        }
    }
#pragma unroll
    for (int o = 0; o < 16; o++) {
        float bv = bias[ocg * 16 + o];
#pragma unroll
        for (int q = 0; q < 4; q++) {
            if (val[q]) {
                float v = acc[q][o] + bv;
                g_h1[(b * 256 + ocg * 16 + o) * 400 + tid + q * 128] = fmaxf(v, 0.f);
            }
        }
    }
}

// ===========================================================================
// merged prep: blocks 0-255 = A quantize (per-oc-row), 256-511 = B per-batch
// max, 512-592 = koff table build. (R16-proven structure.)
// ===========================================================================
__global__ __launch_bounds__(256) void prep_kernel(const float* __restrict__ w2) {
    int blk = blockIdx.x, tid = threadIdx.x;
    if (blk >= 512) {  // koff table
        int k = (blk - 512) * 256 + tid;
        if (k < 20736) {
            int ic = k / 81, rr = k - ic * 81;
            g_koff[k] = ic * 400 + (rr / 9) * 20 + (rr % 9);
        }
        return;
    }
    __shared__ float red[256];
    if (blk < 256) {  // A: row max + 2-limb quantize
        int m = blk;
        const float* row = &w2[(size_t)m * 20736];
        float mx = 0.f;
        for (int k = tid; k < 20736; k += 256) mx = fmaxf(mx, fabsf(row[k]));
        red[tid] = mx;
        __syncthreads();
        for (int s = 128; s > 0; s >>= 1) {
            if (tid < s) red[tid] = fmaxf(red[tid], red[tid + s]);
            __syncthreads();
        }
        mx = red[0];
        if (tid == 0) g_dsA[m] = mx * (1.0f / 16256.0f);
        float qa = mx > 0.f ? 16256.0f / mx : 0.f;
        for (int k = tid; k < 20736; k += 256) {
            float a15 = rintf(row[k] * qa);
            float ahf = rintf(a15 * (1.0f / 128.0f));
            int ah = (int)ahf;
            int al = (int)(a15 - 128.0f * ahf);
            g_w2h8[(size_t)m * 20736 + k] = (char)ah;
            g_w2l8[(size_t)m * 20736 + k] = (char)al;
        }
    } else {  // B: per-batch max of h1
        int b = blk - 256;
        const float* sl = &g_h1[(size_t)b * 102400];
        float mx = 0.f;
        for (int i = tid; i < 102400; i += 256) mx = fmaxf(mx, sl[i]);
        red[tid] = mx;
        __syncthreads();
        for (int s = 128; s > 0; s >>= 1) {
            if (tid < s) red[tid] = fmaxf(red[tid], red[tid + s]);
            __syncthreads();
        }
        if (tid == 0) {
            float m = red[0];
            g_dsB[b] = m * (1.0f / 16256.0f);
            g_qB[b] = m > 0.f ? 16256.0f / m : 0.f;
        }
    }
}

// ===========================================================================
// bquant: im2col B -> two int8 limb planes, via koff lookup (no divisions).
// ===========================================================================
__global__ __launch_bounds__(256) void bquant_kernel() {
    int n = blockIdx.x;
    int bb = n / 36, s = n - bb * 36;
    int base = bb * 102400 + (s / 6) * 40 + (s % 6) * 2;
    float qb = g_qB[bb];
    size_t rowo = (size_t)n * 20736;
    const float* h1b = g_h1 + base;
    for (int k0 = threadIdx.x * 8; k0 < 20736; k0 += 2048) {
        int4 ko0 = *(const int4*)&g_koff[k0];
        int4 ko1 = *(const int4*)&g_koff[k0 + 4];
        int hi[8], lo[8];
        float v[8];
        v[0] = h1b[ko0.x]; v[1] = h1b[ko0.y]; v[2] = h1b[ko0.z]; v[3] = h1b[ko0.w];
        v[4] = h1b[ko1.x]; v[5] = h1b[ko1.y]; v[6] = h1b[ko1.z]; v[7] = h1b[ko1.w];
#pragma unroll
        for (int j = 0; j < 8; j++) {
            int s16 = __float2int_rn(v[j] * qb);
            hi[j] = (s16 + 64) >> 7;
            lo[j] = s16 - (hi[j] << 7);
        }
        uint32_t ph0 = __byte_perm(__byte_perm(hi[0], hi[1], 0x0040),
                                   __byte_perm(hi[2], hi[3], 0x0040), 0x5410);
        uint32_t ph1 = __byte_perm(__byte_perm(hi[4], hi[5], 0x0040),
                                   __byte_perm(hi[6], hi[7], 0x0040), 0x5410);
        uint32_t pl0 = __byte_perm(__byte_perm(lo[0], lo[1], 0x0040),
                                   __byte_perm(lo[2], lo[3], 0x0040), 0x5410);
        uint32_t pl1 = __byte_perm(__byte_perm(lo[4], lo[5], 0x0040),
                                   __byte_perm(lo[6], lo[7], 0x0040), 0x5410);
        *(uint2*)(g_bqh + rowo + k0) = make_uint2(ph0, ph1);
        *(uint2*)(g_bql + rowo + k0) = make_uint2(pl0, pl1);
    }
}

// ===========================================================================
// conv2: pure int8 GEMM (2-limb, 3 MMAs per k32). BK=128, 2-stage ring
// (162 stages, half the per-stage sync overhead of BK=64).
// grid (2,144), 256 thr / 8 warps; warp tile 32x32; 2 CTAs/SM (221KB smem).
// ===========================================================================
#define ROWB 144
#define PLANE_A (128 * ROWB)               // 18432
#define PLANE_B (64 * ROWB)                // 9216
#define STG (2 * PLANE_A + 2 * PLANE_B)    // 55296 per stage (Ah|Al|Bh|Bl)
#define NSTAGE 162

__global__ __launch_bounds__(256, 2) void conv2_mma_kernel(const float* __restrict__ b2) {
    extern __shared__ __align__(16) unsigned char sm[];

    const int tid = threadIdx.x, lane = tid & 31, wid = tid >> 5;
    const int m0 = blockIdx.x * 128, n0 = blockIdx.y * 64;
    const int wm0 = (wid & 3) * 32;
    const int wn0 = (wid >> 2) * 32;
    const uint32_t sb = smem_u32(sm);

    int hh[2][4][4], cr[2][4][4];
#pragma unroll
    for (int mi = 0; mi < 2; mi++)
#pragma unroll
        for (int nt = 0; nt < 4; nt++)
#pragma unroll
            for (int q = 0; q < 4; q++) { hh[mi][nt][q] = 0; cr[mi][nt][q] = 0; }

    auto issue = [&](uint32_t base, int kt) {
#pragma unroll
        for (int q = 0; q < 8; q++) {          // A: 2048 16B chunks
            int id = q * 256 + tid;
            int plane = id >> 10;
            int rem = id & 1023;
            int row = rem >> 3;
            int c16 = rem & 7;
            const char* src = plane ? g_w2l8 : g_w2h8;
            cp16(base + plane * PLANE_A + row * ROWB + c16 * 16,
                 src + (size_t)(m0 + row) * 20736 + kt + c16 * 16);
        }
#pragma unroll
        for (int q = 0; q < 4; q++) {          // B: 1024 16B chunks
            int id = q * 256 + tid;
            int plane = id >> 9;
            int rem = id & 511;
            int row = rem >> 3;
            int c16 = rem & 7;
            const char* src = plane ? g_bql : g_bqh;
            cp16(base + 2 * PLANE_A + plane * PLANE_B + row * ROWB + c16 * 16,
                 src + (size_t)(n0 + row) * 20736 + kt + c16 * 16);
        }
        CP_COMMIT();
    };

    issue(sb, 0);

    for (int s = 0; s < NSTAGE; s++) {
        const uint32_t cb = sb + (uint32_t)(s & 1) * STG;
        CP_WAIT0();       // stage s landed
        __syncthreads();  // all warps done computing previous stage
        if (s + 1 < NSTAGE) issue(sb + (uint32_t)((s + 1) & 1) * STG, (s + 1) * 128);

        // ---- compute: 4 k32-steps x (2m x 4n) x 3 MMAs = 96 MMAs/warp ----
#pragma unroll
        for (int ks = 0; ks < 4; ks++) {
            uint32_t ah[2][4], al[2][4];
#pragma unroll
            for (int mi = 0; mi < 2; mi++) {
                uint32_t ra = (uint32_t)((wm0 + mi * 16 + (lane & 15)) * ROWB +
                                         ks * 32 + ((lane >> 4) << 4));
                ldsm_x4(ah[mi], cb + ra);
                ldsm_x4(al[mi], cb + PLANE_A + ra);
            }
            uint32_t bh[2][4], bl[2][4];
#pragma unroll
            for (int g = 0; g < 2; g++) {
                uint32_t rb = (uint32_t)((wn0 + g * 16 + (lane & 7) + ((lane >> 4) << 3)) * ROWB +
                                         ks * 32 + (((lane >> 3) & 1) << 4));
                ldsm_x4(bh[g], cb + 2 * PLANE_A + rb);
                ldsm_x4(bl[g], cb + 2 * PLANE_A + PLANE_B + rb);
            }
#pragma unroll
            for (int mi = 0; mi < 2; mi++)
#pragma unroll
                for (int g = 0; g < 2; g++)
#pragma unroll
                    for (int h = 0; h < 2; h++) {
                        int nt = g * 2 + h;
                        mma_s8(hh[mi][nt], ah[mi], bh[g][2 * h], bh[g][2 * h + 1]);
                        mma_s8(cr[mi][nt], ah[mi], bl[g][2 * h], bl[g][2 * h + 1]);
                        mma_s8(cr[mi][nt], al[mi], bh[g][2 * h], bh[g][2 * h + 1]);
                    }
        }
    }

#pragma unroll
    for (int mi = 0; mi < 2; mi++) {
        int r0 = m0 + wm0 + mi * 16 + (lane >> 2);
        int r1 = r0 + 8;
        float sa0 = g_dsA[r0], sa1 = g_dsA[r1];
        float bias0 = b2[r0], bias1 = b2[r1];
#pragma unroll
        for (int nt = 0; nt < 4; nt++) {
            int c0 = n0 + wn0 + nt * 8 + ((lane & 3) << 1);
            int c1 = c0 + 1;
            int bb0 = c0 / 36, ss0 = c0 - bb0 * 36;
            int bb1 = c1 / 36, ss1 = c1 - bb1 * 36;
            float s0 = g_dsB[bb0], s1 = g_dsB[bb1];
            g_uraw[bb0 * 9216 + ss0 + r0 * 36] =
                sa0 * s0 * (16384.f * (float)hh[mi][nt][0] + 128.f * (float)cr[mi][nt][0]) + bias0;
            g_uraw[bb1 * 9216 + ss1 + r0 * 36] =
                sa0 * s1 * (16384.f * (float)hh[mi][nt][1] + 128.f * (float)cr[mi][nt][1]) + bias0;
            g_uraw[bb0 * 9216 + ss0 + r1 * 36] =
                sa1 * s0 * (16384.f * (float)hh[mi][nt][2] + 128.f * (float)cr[mi][nt][2]) + bias1;
            g_uraw[bb1 * 9216 + ss1 + r1 * 36] =
                sa1 * s1 * (16384.f * (float)hh[mi][nt][3] + 128.f * (float)cr[mi][nt][3]) + bias1;
        }
    }
}

// ===========================================================================
// primary squash + transpose
// ===========================================================================
__global__ __launch_bounds__(256) void squashT_kernel() {
    int idx = blockIdx.x * 256 + threadIdx.x;
    int n = idx >> 8, b = idx & 255;
    const float4* src = (const float4*)&g_uraw[b * 9216 + n * 8];
    float4 u0 = src[0], u1 = src[1];
    float sq = u0.x * u0.x + u0.y * u0.y + u0.z * u0.z + u0.w * u0.w +
               u1.x * u1.x + u1.y * u1.y + u1.z * u1.z + u1.w * u1.w;
    float sc = sq / (1.0f + sq);
    float r[8] = {u0.x * sc, u0.y * sc, u0.z * sc, u0.w * sc,
                  u1.x * sc, u1.y * sc, u1.z * sc, u1.w * sc};
#pragma unroll
    for (int j = 0; j < 8; j++) g_uT[(n * 8 + j) * 256 + b] = r[j];
}

__global__ __launch_bounds__(128) void softmax_kernel() {
    int c = blockIdx.x >> 4, i = blockIdx.x & 15;
    int tid = threadIdx.x;
    __shared__ float red[128];
    float vals[9];
    float m = -1e30f;
#pragma unroll
    for (int q = 0; q < 9; q++) {
        int n = tid + q * 128;
        vals[q] = g_blog[(c * 1152 + n) * 16 + i];
        m = fmaxf(m, vals[q]);
    }
    red[tid] = m;
    __syncthreads();
    for (int s2 = 64; s2 > 0; s2 >>= 1) {
        if (tid < s2) red[tid] = fmaxf(red[tid], red[tid + s2]);
        __syncthreads();
    }
    float M = red[0];
    __syncthreads();
    float e[9];
    float sum = 0.f;
#pragma unroll
    for (int q = 0; q < 9; q++) {
        e[q] = expf(vals[q] - M);
        sum += e[q];
    }
    red[tid] = sum;
    __syncthreads();
    for (int s2 = 64; s2 > 0; s2 >>= 1) {
        if (tid < s2) red[tid] += red[tid + s2];
        __syncthreads();
    }
    float inv = 1.0f / red[0];
#pragma unroll
    for (int q = 0; q < 9; q++)
        g_probs[(c * 1152 + tid + q * 128) * 16 + i] = e[q] * inv;
}

// ===========================================================================
// s partial GEMM: 32 n-chunks of 36. uniform=1: probs = 1/1152 (iter 0).
// ===========================================================================
__global__ __launch_bounds__(128) void sgemm_routing_kernel(const float* __restrict__ W,
                                                            int uniform) {
    int nc = blockIdx.x, c = blockIdx.y;
    int tid = threadIdx.x;
    int ig = tid >> 5, bg = tid & 31;
    int i0 = ig << 2;
    __shared__ float uu[2048];
    __shared__ float pw[128];
    int pi = tid >> 3, pj = tid & 7;

    float acc[4][8];
#pragma unroll
    for (int ii = 0; ii < 4; ii++)
#pragma unroll
        for (int bi = 0; bi < 8; bi++) acc[ii][bi] = 0.f;

    for (int n = nc * 36; n < nc * 36 + 36; ++n) {
        __syncthreads();
        const float4* src = (const float4*)&g_uT[n * 2048];
#pragma unroll
        for (int q = 0; q < 4; q++) ((float4*)uu)[tid + q * 128] = src[tid + q * 128];
        float p = uniform ? (1.0f / 1152.0f) : g_probs[(c * 1152 + n) * 16 + pi];
        pw[tid] = p * W[((c * 1152 + n) * 16 + pi) * 8 + pj];
        __syncthreads();

        float pwv[4][8];
#pragma unroll
        for (int ii = 0; ii < 4; ii++)
#pragma unroll
            for (int j = 0; j < 8; j++) pwv[ii][j] = pw[(i0 + ii) * 8 + j];

#pragma unroll
        for (int bi = 0; bi < 8; bi++) {
            int b = bg + (bi << 5);
            float uv[8];
#pragma unroll
            for (int j = 0; j < 8; j++) uv[j] = uu[j * 256 + b];
#pragma unroll
            for (int ii = 0; ii < 4; ii++)
#pragma unroll
                for (int j = 0; j < 8; j++)
                    acc[ii][bi] = fmaf(pwv[ii][j], uv[j], acc[ii][bi]);
        }
    }
#pragma unroll
    for (int ii = 0; ii < 4; ii++)
#pragma unroll
        for (int bi = 0; bi < 8; bi++)
            g_spart[((c * 32 + nc) * 16 + i0 + ii) * 256 + bg + (bi << 5)] = acc[ii][bi];
}

__global__ __launch_bounds__(256) void squashv_kernel() {
    int c = blockIdx.x >> 4, i = blockIdx.x & 15;
    int tid = threadIdx.x;
    float sv = 0.f;
#pragma unroll
    for (int ch = 0; ch < 32; ch++)
        sv += g_spart[((c * 32 + ch) * 16 + i) * 256 + tid];
    __shared__ float red[256];
    red[tid] = sv * sv;
    __syncthreads();
    for (int s2 = 128; s2 > 0; s2 >>= 1) {
        if (tid < s2) red[tid] += red[tid + s2];
        __syncthreads();
    }
    float sq = red[0];
    float scale = sq / ((1.0f + sq) * sqrtf(sq));
    g_v[(c * 16 + i) * 256 + tid] = sv * scale;
}

// store=1: first delta (blog starts undefined; overwrite). Else accumulate.
__global__ __launch_bounds__(128) void delta_kernel(const float* __restrict__ W,
                                                    int store) {
    int n0 = blockIdx.x * 8, c = blockIdx.y;
    int tid = threadIdx.x;
    int nl = tid >> 4, i = tid & 15;
    int n = n0 + nl;
    __shared__ float vsh[16 * 257];
    __shared__ float ush[2048];
    float wr[8];
    const float* wp = &W[((c * 1152 + n) * 16 + i) * 8];
#pragma unroll
    for (int j = 0; j < 8; j++) wr[j] = wp[j];
#pragma unroll
    for (int q = 0; q < 32; q++) {
        int idx = tid + q * 128;
        vsh[(idx >> 8) * 257 + (idx & 255)] = g_v[c * 4096 + idx];
    }
    float acc = 0.f;
    for (int bc = 0; bc < 8; bc++) {
        __syncthreads();
#pragma unroll
        for (int q = 0; q < 16; q++) {
            int f = tid + q * 128;
            ush[f] = g_uT[(n0 * 8 + (f >> 5)) * 256 + (bc << 5) + (f & 31)];
        }
        __syncthreads();
#pragma unroll 4
        for (int bb = 0; bb < 32; bb++) {
            int b = (bc << 5) + bb;
            float uh = 0.f;
#pragma unroll
            for (int j = 0; j < 8; j++)
                uh = fmaf(wr[j], ush[(nl * 8 + j) * 32 + bb], uh);
            acc = fmaf(uh, vsh[i * 257 + b], acc);
        }
    }
    int idx = (c * 1152 + n) * 16 + i;
    g_blog[idx] = store ? acc : (g_blog[idx] + acc);
}

__global__ void out_kernel(float* __restrict__ out) {
    int c = blockIdx.x, b = threadIdx.x;
    float s = 0.f;
#pragma unroll
    for (int i = 0; i < 16; i++) {
        float t = g_v[(c * 16 + i) * 256 + b];
        s = fmaf(t, t, s);
    }
    out[b * 10 + c] = s;
}

// ===========================================================================
extern "C" void kernel_launch(void* const* d_in, const int* in_sizes, int n_in,
                              void* d_out, int out_size) {
    const float* x  = (const float*)d_in[0];
    const float* w1 = (const float*)d_in[1];
    const float* b1 = (const float*)d_in[2];
    const float* w2 = (const float*)d_in[3];
    const float* b2 = (const float*)d_in[4];
    const float* W  = (const float*)d_in[5];
    float* out = (float*)d_out;

    const int SMEM_BYTES = 2 * STG;  // 110592
    cudaFuncSetAttribute(conv2_mma_kernel, cudaFuncAttributeMaxDynamicSharedMemorySize,
                         SMEM_BYTES);

    conv1_kernel<<<dim3(256, 16), 128>>>(x, w1, b1);
    prep_kernel<<<593, 256>>>(w2);
    bquant_kernel<<<9216, 256>>>();
    conv2_mma_kernel<<<dim3(2, 144), 256, SMEM_BYTES>>>(b2);
    squashT_kernel<<<1152, 256>>>();

    for (int it = 0; it < 3; it++) {
        if (it > 0) softmax_kernel<<<160, 128>>>();
        sgemm_routing_kernel<<<dim3(32, 10), 128>>>(W, it == 0 ? 1 : 0);
        squashv_kernel<<<160, 256>>>();
        if (it < 2) delta_kernel<<<dim3(144, 10), 128>>>(W, it == 0 ? 1 : 0);
    }
    out_kernel<<<10, 256>>>(out);
}